// round 15
// baseline (speedup 1.0000x reference)
#include <cuda_runtime.h>
#include <math.h>

// Problem constants (B=4, T=2048, D=1024, E=8, K=2)
#define BT           8192
#define DD           1024
#define EE           8
#define TPB          256
#define ROWS_PER_CTA 16
#define NCTA         (BT / ROWS_PER_CTA)   // 512

__device__ float        g_aux_part[NCTA];
__device__ unsigned int g_ctr;             // zero-init; self-resets each launch

// Hierarchical reduce: 16 accs (2 rows x 8 experts) over 32 lanes, 31 SHFLs.
// Returns: lane L holds the logit for row = bit3(L), e = L & 7.
__device__ __forceinline__ float pair_reduce(float* acc0, float* acc1, int lane) {
#pragma unroll
    for (int j = 0; j < EE; j++) {
        acc0[j] += __shfl_xor_sync(0xffffffffu, acc0[j], 16);
        acc1[j] += __shfl_xor_sync(0xffffffffu, acc1[j], 16);
    }
    const bool rsel = (lane & 8) != 0;
    float t[8];
#pragma unroll
    for (int j = 0; j < EE; j++) {
        float send = rsel ? acc0[j] : acc1[j];
        float recv = __shfl_xor_sync(0xffffffffu, send, 8);
        t[j] = (rsel ? acc1[j] : acc0[j]) + recv;
    }
    const bool hi = (lane & 4) != 0;
    float u4[4];
#pragma unroll
    for (int k = 0; k < 4; k++) {
        float send = hi ? t[k] : t[k + 4];
        float recv = __shfl_xor_sync(0xffffffffu, send, 4);
        u4[k] = (hi ? t[k + 4] : t[k]) + recv;
    }
    const bool b1 = (lane & 2) != 0;
    float w2[2];
#pragma unroll
    for (int k = 0; k < 2; k++) {
        float send = b1 ? u4[k] : u4[k + 2];
        float recv = __shfl_xor_sync(0xffffffffu, send, 2);
        w2[k] = (b1 ? u4[k + 2] : u4[k]) + recv;
    }
    const bool b0 = (lane & 1) != 0;
    float send = b0 ? w2[0] : w2[1];
    float recv = __shfl_xor_sync(0xffffffffu, send, 1);
    return (b0 ? w2[1] : w2[0]) + recv;
}

// Lane-parallel softmax + gumbel top-2 (lane = row*8+e layout within 8-groups).
__device__ __forceinline__ void softmax_top2(
    float le, int lane, int row,
    const float* __restrict__ bias, const float* __restrict__ noise,
    const float* __restrict__ rewards, const float* __restrict__ baseline,
    int& i0, int& i1, float& auxv)
{
    const int e = lane & 7;
    le += __ldg(bias + e);

    float m = le;
#pragma unroll
    for (int off = 4; off; off >>= 1)
        m = fmaxf(m, __shfl_xor_sync(0xffffffffu, m, off));
    float p = __expf(le - m);
    float s = p;
#pragma unroll
    for (int off = 4; off; off >>= 1)
        s += __shfl_xor_sync(0xffffffffu, s, off);
    float lp = __logf(p / s + 1e-9f);         // absolute-error safe

    float u = __ldg(noise + (size_t)row * EE + e) * (1.0f - 2e-7f) + 1e-7f;
    float y = lp - __logf(-logf(u));          // inner log kept precise

    float by = y; int bi = e;
#pragma unroll
    for (int off = 4; off; off >>= 1) {
        float oy = __shfl_xor_sync(0xffffffffu, by, off);
        int   oi = __shfl_xor_sync(0xffffffffu, bi, off);
        if (oy > by || (oy == by && oi < bi)) { by = oy; bi = oi; }
    }
    i0 = bi;
    float y2 = (e == i0) ? -1e30f : y;
    float by2 = y2; int bi2 = e;
#pragma unroll
    for (int off = 4; off; off >>= 1) {
        float oy = __shfl_xor_sync(0xffffffffu, by2, off);
        int   oi = __shfl_xor_sync(0xffffffffu, bi2, off);
        if (oy > by2 || (oy == by2 && oi < bi2)) { by2 = oy; bi2 = oi; }
    }
    i1 = bi2;

    float lp0 = __shfl_sync(0xffffffffu, lp, (lane & 24) | i0);
    float lp1 = __shfl_sync(0xffffffffu, lp, (lane & 24) | i1);
    float adv = __ldg(rewards + row) - __ldg(baseline);
    auxv = adv * (lp0 + lp1);
}

// Stream two rows (4 loads in flight per iteration).
__device__ __forceinline__ void stream_two_rows(
    const float* __restrict__ eo, float* __restrict__ out,
    int rowX, int iX0, int iX1, int rowY, int iY0, int iY1, int lane)
{
    const float4* qa = (const float4*)(eo + ((size_t)iX0 * BT + rowX) * DD);
    const float4* qb = (const float4*)(eo + ((size_t)iX1 * BT + rowX) * DD);
    const float4* qc = (const float4*)(eo + ((size_t)iY0 * BT + rowY) * DD);
    const float4* qd = (const float4*)(eo + ((size_t)iY1 * BT + rowY) * DD);
    float4* oX = (float4*)(out + (size_t)rowX * DD);
    float4* oY = (float4*)(out + (size_t)rowY * DD);
#pragma unroll
    for (int i = 0; i < 8; i++) {
        int j = lane + 32 * i;
        float4 va = __ldcs(qa + j);
        float4 vb = __ldcs(qb + j);
        float4 vc = __ldcs(qc + j);
        float4 vd = __ldcs(qd + j);
        float4 rX, rY;
        rX.x = (va.x + vb.x) * 0.5f;  rX.y = (va.y + vb.y) * 0.5f;
        rX.z = (va.z + vb.z) * 0.5f;  rX.w = (va.w + vb.w) * 0.5f;
        rY.x = (vc.x + vd.x) * 0.5f;  rY.y = (vc.y + vd.y) * 0.5f;
        rY.z = (vc.z + vd.z) * 0.5f;  rY.w = (vc.w + vd.w) * 0.5f;
        __stcs(oX + j, rX);
        __stcs(oY + j, rY);
    }
}

// Stream one row, 2 j-positions per step (4 loads in flight).
__device__ __forceinline__ void stream_one_row(
    const float* __restrict__ eo, float* __restrict__ out,
    int row, int i0, int i1, int lane)
{
    const float4* qa = (const float4*)(eo + ((size_t)i0 * BT + row) * DD);
    const float4* qb = (const float4*)(eo + ((size_t)i1 * BT + row) * DD);
    float4* o = (float4*)(out + (size_t)row * DD);
#pragma unroll
    for (int i = 0; i < 8; i += 2) {
        int j0 = lane + 32 * i;
        int j1 = lane + 32 * (i + 1);
        float4 va0 = __ldcs(qa + j0);
        float4 vb0 = __ldcs(qb + j0);
        float4 va1 = __ldcs(qa + j1);
        float4 vb1 = __ldcs(qb + j1);
        float4 r0, r1;
        r0.x = (va0.x + vb0.x) * 0.5f;  r0.y = (va0.y + vb0.y) * 0.5f;
        r0.z = (va0.z + vb0.z) * 0.5f;  r0.w = (va0.w + vb0.w) * 0.5f;
        r1.x = (va1.x + vb1.x) * 0.5f;  r1.y = (va1.y + vb1.y) * 0.5f;
        r1.z = (va1.z + vb1.z) * 0.5f;  r1.w = (va1.w + vb1.w) * 0.5f;
        __stcs(o + j0, r0);
        __stcs(o + j1, r1);
    }
}

__global__ __launch_bounds__(TPB, 4) void rlgate_main_kernel(
    const float* __restrict__ x,          // [BT, D]
    const float* __restrict__ eo,         // [E, BT, D]
    const float* __restrict__ rewards,    // [BT]
    const float* __restrict__ W,          // [D, E]
    const float* __restrict__ bias,       // [E]
    const float* __restrict__ baseline,   // scalar
    const float* __restrict__ noise,      // [BT, E]
    float* __restrict__ out,              // [BT*D (+aux slot)]
    int out_size)
{
    __shared__ int   s_i0[ROWS_PER_CTA];
    __shared__ int   s_i1[ROWS_PER_CTA];
    __shared__ int   s_flag[8];           // one per produced pair
    __shared__ float s_aux[ROWS_PER_CTA];

    const int tid  = threadIdx.x;
    const int lane = tid & 31;
    const int warp = tid >> 5;            // 0..7

    if (tid < 8) s_flag[tid] = 0;
    __syncthreads();

    const int cta_base = blockIdx.x * ROWS_PER_CTA;

    if (warp < 4) {
        // ================= GATE producer (one per SMSP) =================
        const int g    = warp;
        const int base = cta_base + 4 * g;      // rows base..base+3
        const float4* Wb = (const float4*)W;    // W[d][e]: row d = 2 float4s

        int last0 = 0, last1 = 0;               // indices of row base+3

#pragma unroll
        for (int p = 0; p < 2; p++) {
            const int r0 = base + 2 * p;
            const int r1 = r0 + 1;
            const float4* x0 = (const float4*)(x + (size_t)r0 * DD);
            const float4* x1 = (const float4*)(x + (size_t)r1 * DD);

            float4 pa[4], pb[4];
#pragma unroll
            for (int k = 0; k < 4; k++) {
                pa[k] = __ldg(x0 + lane + 32 * k);
                pb[k] = __ldg(x1 + lane + 32 * k);
            }

            float acc0[EE], acc1[EE];
#pragma unroll
            for (int e = 0; e < EE; e++) { acc0[e] = 0.0f; acc1[e] = 0.0f; }

#pragma unroll
            for (int i = 0; i < 8; i++) {
                float4 a4 = pa[i & 3];
                float4 b4 = pb[i & 3];
                if (i < 4) {
                    int jn = lane + 32 * (i + 4);
                    pa[i & 3] = __ldg(x0 + jn);
                    pb[i & 3] = __ldg(x1 + jn);
                }
                const int j = lane + 32 * i;     // float4 index; d = 4j..4j+3
#pragma unroll
                for (int r = 0; r < 4; r++) {
                    const int d = 4 * j + r;
                    float4 wlo = __ldg(Wb + 2 * d);      // experts 0..3
                    float4 whi = __ldg(Wb + 2 * d + 1);  // experts 4..7
                    float xa = (r == 0) ? a4.x : (r == 1) ? a4.y : (r == 2) ? a4.z : a4.w;
                    float xb = (r == 0) ? b4.x : (r == 1) ? b4.y : (r == 2) ? b4.z : b4.w;
                    acc0[0] = fmaf(xa, wlo.x, acc0[0]);
                    acc0[1] = fmaf(xa, wlo.y, acc0[1]);
                    acc0[2] = fmaf(xa, wlo.z, acc0[2]);
                    acc0[3] = fmaf(xa, wlo.w, acc0[3]);
                    acc0[4] = fmaf(xa, whi.x, acc0[4]);
                    acc0[5] = fmaf(xa, whi.y, acc0[5]);
                    acc0[6] = fmaf(xa, whi.z, acc0[6]);
                    acc0[7] = fmaf(xa, whi.w, acc0[7]);
                    acc1[0] = fmaf(xb, wlo.x, acc1[0]);
                    acc1[1] = fmaf(xb, wlo.y, acc1[1]);
                    acc1[2] = fmaf(xb, wlo.z, acc1[2]);
                    acc1[3] = fmaf(xb, wlo.w, acc1[3]);
                    acc1[4] = fmaf(xb, whi.x, acc1[4]);
                    acc1[5] = fmaf(xb, whi.y, acc1[5]);
                    acc1[6] = fmaf(xb, whi.z, acc1[6]);
                    acc1[7] = fmaf(xb, whi.w, acc1[7]);
                }
            }

            float le = pair_reduce(acc0, acc1, lane);
            const int half = (lane >> 3) & 1;
            const int row  = half ? r1 : r0;
            int i0, i1; float auxv;
            softmax_top2(le, lane, row, bias, noise, rewards, baseline, i0, i1, auxv);

            const int lrow = 4 * g + 2 * p + half;   // local row index
            if (lane < 16 && (lane & 7) == 0) {      // lanes 0 and 8
                s_aux[lrow] = auxv;
                s_i0[lrow]  = i0;
                s_i1[lrow]  = i1;
            }
            __threadfence_block();
            if (lane == 0)
                ((volatile int*)s_flag)[2 * g + p] = 1;

            if (p == 1) {                            // remember row base+3's pick
                last0 = __shfl_sync(0xffffffffu, i0, 8);
                last1 = __shfl_sync(0xffffffffu, i1, 8);
            }
        }

        // Producer streams its last-produced row (no wait needed).
        stream_one_row(eo, out, base + 3, last0, last1, lane);
    } else {
        // ================= STREAM consumer =================
        const int g    = warp - 4;
        const int base = cta_base + 4 * g;

        // Wait for pair 0 of gate warp g -> stream rows base, base+1.
        if (lane == 0) {
            while (((volatile int*)s_flag)[2 * g] == 0) __nanosleep(32);
        }
        __syncwarp();
        __threadfence_block();
        int a0 = s_i0[4 * g + 0], a1 = s_i1[4 * g + 0];
        int b0 = s_i0[4 * g + 1], b1 = s_i1[4 * g + 1];
        stream_two_rows(eo, out, base, a0, a1, base + 1, b0, b1, lane);

        // Wait for pair 1 -> stream row base+2 (base+3 handled by producer).
        if (lane == 0) {
            while (((volatile int*)s_flag)[2 * g + 1] == 0) __nanosleep(32);
        }
        __syncwarp();
        __threadfence_block();
        int c0 = s_i0[4 * g + 2], c1 = s_i1[4 * g + 2];
        stream_one_row(eo, out, base + 2, c0, c1, lane);
    }

    // ---- Aux finale (single barrier) ----
    __syncthreads();
    if (warp == 0) {
        int is_last = 0;
        if (lane == 0) {
            float s = 0.0f;
#pragma unroll
            for (int i = 0; i < ROWS_PER_CTA; i++) s += s_aux[i];
            g_aux_part[blockIdx.x] = s;
            __threadfence();
            unsigned p = atomicAdd(&g_ctr, 1u);
            is_last = (p == NCTA - 1);
        }
        is_last = __shfl_sync(0xffffffffu, is_last, 0);
        if (is_last) {
            double s = 0.0;
#pragma unroll
            for (int k = 0; k < NCTA / 32; k++)
                s += (double)__ldcg(&g_aux_part[lane + 32 * k]);
#pragma unroll
            for (int off = 16; off > 0; off >>= 1)
                s += __shfl_xor_sync(0xffffffffu, s, off);
            if (lane == 0) {
                out[out_size - 1] = -(float)(s / (double)BT);
                g_ctr = 0;                    // reset for next graph replay
            }
        }
    }
}

extern "C" void kernel_launch(void* const* d_in, const int* in_sizes, int n_in,
                              void* d_out, int out_size) {
    const float* x        = (const float*)d_in[0];
    const float* eo       = (const float*)d_in[1];
    const float* rewards  = (const float*)d_in[2];
    const float* W        = (const float*)d_in[3];
    const float* bias     = (const float*)d_in[4];
    const float* baseline = (const float*)d_in[5];
    const float* noise    = (const float*)d_in[6];
    // d_in[7] = top_k (K=2 hardcoded to match problem shapes)
    float* out = (float*)d_out;

    rlgate_main_kernel<<<NCTA, TPB>>>(x, eo, rewards, W, bias, baseline, noise,
                                      out, out_size);
}

// round 16
// speedup vs baseline: 1.7990x; 1.7990x over previous
#include <cuda_runtime.h>
#include <math.h>

// Problem constants (B=4, T=2048, D=1024, E=8, K=2)
#define BT           8192
#define DD           1024
#define EE           8
#define TPB          256
#define ROWS_PER_CTA 16
#define NCTA         (BT / ROWS_PER_CTA)   // 512

__device__ float        g_aux_part[NCTA];
__device__ unsigned int g_ctr;             // zero-init; self-resets each launch

// Hierarchical reduce: 16 accs (2 rows x 8 experts) over 32 lanes, 31 SHFLs.
// Returns: lane L holds the logit for row = bit3(L), e = L & 7.
__device__ __forceinline__ float pair_reduce(float* acc0, float* acc1, int lane) {
#pragma unroll
    for (int j = 0; j < EE; j++) {
        acc0[j] += __shfl_xor_sync(0xffffffffu, acc0[j], 16);
        acc1[j] += __shfl_xor_sync(0xffffffffu, acc1[j], 16);
    }
    const bool rsel = (lane & 8) != 0;
    float t[8];
#pragma unroll
    for (int j = 0; j < EE; j++) {
        float send = rsel ? acc0[j] : acc1[j];
        float recv = __shfl_xor_sync(0xffffffffu, send, 8);
        t[j] = (rsel ? acc1[j] : acc0[j]) + recv;
    }
    const bool hi = (lane & 4) != 0;
    float u4[4];
#pragma unroll
    for (int k = 0; k < 4; k++) {
        float send = hi ? t[k] : t[k + 4];
        float recv = __shfl_xor_sync(0xffffffffu, send, 4);
        u4[k] = (hi ? t[k + 4] : t[k]) + recv;
    }
    const bool b1 = (lane & 2) != 0;
    float w2[2];
#pragma unroll
    for (int k = 0; k < 2; k++) {
        float send = b1 ? u4[k] : u4[k + 2];
        float recv = __shfl_xor_sync(0xffffffffu, send, 2);
        w2[k] = (b1 ? u4[k + 2] : u4[k]) + recv;
    }
    const bool b0 = (lane & 1) != 0;
    float send = b0 ? w2[0] : w2[1];
    float recv = __shfl_xor_sync(0xffffffffu, send, 1);
    return (b0 ? w2[1] : w2[0]) + recv;
}

// Lane-parallel softmax + gumbel top-2 (lane = row*8+e layout within 8-groups).
__device__ __forceinline__ void softmax_top2(
    float le, int lane, int row,
    const float* __restrict__ bias, const float* __restrict__ noise,
    const float* __restrict__ rewards, const float* __restrict__ baseline,
    int& i0, int& i1, float& auxv)
{
    const int e = lane & 7;
    le += __ldg(bias + e);

    float m = le;
#pragma unroll
    for (int off = 4; off; off >>= 1)
        m = fmaxf(m, __shfl_xor_sync(0xffffffffu, m, off));
    float p = __expf(le - m);
    float s = p;
#pragma unroll
    for (int off = 4; off; off >>= 1)
        s += __shfl_xor_sync(0xffffffffu, s, off);
    float lp = __logf(p / s + 1e-9f);         // absolute-error safe

    float u = __ldg(noise + (size_t)row * EE + e) * (1.0f - 2e-7f) + 1e-7f;
    float y = lp - __logf(-logf(u));          // inner log kept precise

    float by = y; int bi = e;
#pragma unroll
    for (int off = 4; off; off >>= 1) {
        float oy = __shfl_xor_sync(0xffffffffu, by, off);
        int   oi = __shfl_xor_sync(0xffffffffu, bi, off);
        if (oy > by || (oy == by && oi < bi)) { by = oy; bi = oi; }
    }
    i0 = bi;
    float y2 = (e == i0) ? -1e30f : y;
    float by2 = y2; int bi2 = e;
#pragma unroll
    for (int off = 4; off; off >>= 1) {
        float oy = __shfl_xor_sync(0xffffffffu, by2, off);
        int   oi = __shfl_xor_sync(0xffffffffu, bi2, off);
        if (oy > by2 || (oy == by2 && oi < bi2)) { by2 = oy; bi2 = oi; }
    }
    i1 = bi2;

    float lp0 = __shfl_sync(0xffffffffu, lp, (lane & 24) | i0);
    float lp1 = __shfl_sync(0xffffffffu, lp, (lane & 24) | i1);
    float adv = __ldg(rewards + row) - __ldg(baseline);
    auxv = adv * (lp0 + lp1);
}

// Stream two rows (4 loads in flight per iteration).
__device__ __forceinline__ void stream_two_rows(
    const float* __restrict__ eo, float* __restrict__ out,
    int rowX, int iX0, int iX1, int rowY, int iY0, int iY1, int lane)
{
    const float4* qa = (const float4*)(eo + ((size_t)iX0 * BT + rowX) * DD);
    const float4* qb = (const float4*)(eo + ((size_t)iX1 * BT + rowX) * DD);
    const float4* qc = (const float4*)(eo + ((size_t)iY0 * BT + rowY) * DD);
    const float4* qd = (const float4*)(eo + ((size_t)iY1 * BT + rowY) * DD);
    float4* oX = (float4*)(out + (size_t)rowX * DD);
    float4* oY = (float4*)(out + (size_t)rowY * DD);
#pragma unroll
    for (int i = 0; i < 8; i++) {
        int j = lane + 32 * i;
        float4 va = __ldcs(qa + j);
        float4 vb = __ldcs(qb + j);
        float4 vc = __ldcs(qc + j);
        float4 vd = __ldcs(qd + j);
        float4 rX, rY;
        rX.x = (va.x + vb.x) * 0.5f;  rX.y = (va.y + vb.y) * 0.5f;
        rX.z = (va.z + vb.z) * 0.5f;  rX.w = (va.w + vb.w) * 0.5f;
        rY.x = (vc.x + vd.x) * 0.5f;  rY.y = (vc.y + vd.y) * 0.5f;
        rY.z = (vc.z + vd.z) * 0.5f;  rY.w = (vc.w + vd.w) * 0.5f;
        __stcs(oX + j, rX);
        __stcs(oY + j, rY);
    }
}

// Stream one row, 2 j-positions per step (4 loads in flight).
__device__ __forceinline__ void stream_one_row(
    const float* __restrict__ eo, float* __restrict__ out,
    int row, int i0, int i1, int lane)
{
    const float4* qa = (const float4*)(eo + ((size_t)i0 * BT + row) * DD);
    const float4* qb = (const float4*)(eo + ((size_t)i1 * BT + row) * DD);
    float4* o = (float4*)(out + (size_t)row * DD);
#pragma unroll
    for (int i = 0; i < 8; i += 2) {
        int j0 = lane + 32 * i;
        int j1 = lane + 32 * (i + 1);
        float4 va0 = __ldcs(qa + j0);
        float4 vb0 = __ldcs(qb + j0);
        float4 va1 = __ldcs(qa + j1);
        float4 vb1 = __ldcs(qb + j1);
        float4 r0, r1;
        r0.x = (va0.x + vb0.x) * 0.5f;  r0.y = (va0.y + vb0.y) * 0.5f;
        r0.z = (va0.z + vb0.z) * 0.5f;  r0.w = (va0.w + vb0.w) * 0.5f;
        r1.x = (va1.x + vb1.x) * 0.5f;  r1.y = (va1.y + vb1.y) * 0.5f;
        r1.z = (va1.z + vb1.z) * 0.5f;  r1.w = (va1.w + vb1.w) * 0.5f;
        __stcs(o + j0, r0);
        __stcs(o + j1, r1);
    }
}

__global__ __launch_bounds__(TPB, 4) void rlgate_main_kernel(
    const float* __restrict__ x,          // [BT, D]
    const float* __restrict__ eo,         // [E, BT, D]
    const float* __restrict__ rewards,    // [BT]
    const float* __restrict__ W,          // [D, E]
    const float* __restrict__ bias,      // [E]
    const float* __restrict__ baseline,   // scalar
    const float* __restrict__ noise,      // [BT, E]
    float* __restrict__ out,              // [BT*D (+aux slot)]
    int out_size)
{
    __shared__ float Wt[EE][DD];          // transposed gate weights, 32KB
    __shared__ int   s_i0[ROWS_PER_CTA];
    __shared__ int   s_i1[ROWS_PER_CTA];
    __shared__ int   s_flag[8];           // one per produced pair
    __shared__ float s_aux[ROWS_PER_CTA];

    const int tid  = threadIdx.x;
    const int lane = tid & 31;
    const int warp = tid >> 5;            // 0..7

    if (tid < 8) s_flag[tid] = 0;

    // ---- All warps fill W [D,E] -> smem transposed Wt[E][D] ----
    {
        const float4* W4 = (const float4*)W;
#pragma unroll
        for (int k = 0; k < (DD * EE / 4) / TPB; k++) {
            int i = tid + k * TPB;
            float4 v = __ldg(W4 + i);
            int d  = i >> 1;
            int e0 = (i & 1) * 4;
            Wt[e0 + 0][d] = v.x;
            Wt[e0 + 1][d] = v.y;
            Wt[e0 + 2][d] = v.z;
            Wt[e0 + 3][d] = v.w;
        }
    }
    __syncthreads();

    const int cta_base = blockIdx.x * ROWS_PER_CTA;
    const float4* Wt4 = (const float4*)Wt;   // Wt4[e*256 + j]

    if (warp < 4) {
        // ================= GATE producer (one per SMSP) =================
        const int g    = warp;
        const int base = cta_base + 4 * g;      // rows base..base+3

        int last0 = 0, last1 = 0;               // picks of row base+3

#pragma unroll
        for (int p = 0; p < 2; p++) {
            const int r0 = base + 2 * p;
            const int r1 = r0 + 1;
            const float4* x0 = (const float4*)(x + (size_t)r0 * DD);
            const float4* x1 = (const float4*)(x + (size_t)r1 * DD);

            float4 pa[4], pb[4];
#pragma unroll
            for (int k = 0; k < 4; k++) {
                pa[k] = __ldg(x0 + lane + 32 * k);
                pb[k] = __ldg(x1 + lane + 32 * k);
            }

            float acc0[EE], acc1[EE];
#pragma unroll
            for (int e = 0; e < EE; e++) { acc0[e] = 0.0f; acc1[e] = 0.0f; }

#pragma unroll
            for (int i = 0; i < 8; i++) {
                float4 a4 = pa[i & 3];
                float4 b4 = pb[i & 3];
                if (i < 4) {
                    int jn = lane + 32 * (i + 4);
                    pa[i & 3] = __ldg(x0 + jn);
                    pb[i & 3] = __ldg(x1 + jn);
                }
                int j = lane + 32 * i;
#pragma unroll
                for (int e = 0; e < EE; e++) {
                    float4 w = Wt4[e * (DD / 4) + j];   // conflict-free LDS.128
                    acc0[e] = fmaf(a4.x, w.x, fmaf(a4.y, w.y, fmaf(a4.z, w.z, fmaf(a4.w, w.w, acc0[e]))));
                    acc1[e] = fmaf(b4.x, w.x, fmaf(b4.y, w.y, fmaf(b4.z, w.z, fmaf(b4.w, w.w, acc1[e]))));
                }
            }

            float le = pair_reduce(acc0, acc1, lane);
            const int half = (lane >> 3) & 1;
            const int row  = half ? r1 : r0;
            int i0, i1; float auxv;
            softmax_top2(le, lane, row, bias, noise, rewards, baseline, i0, i1, auxv);

            const int lrow = 4 * g + 2 * p + half;   // local row index
            if (lane < 16 && (lane & 7) == 0) {      // lanes 0 and 8
                s_aux[lrow] = auxv;
                s_i0[lrow]  = i0;
                s_i1[lrow]  = i1;
            }
            __threadfence_block();
            if (lane == 0)
                ((volatile int*)s_flag)[2 * g + p] = 1;

            if (p == 1) {                            // row base+3's picks
                last0 = __shfl_sync(0xffffffffu, i0, 8);
                last1 = __shfl_sync(0xffffffffu, i1, 8);
            }
        }

        // Producer streams its last-produced row (no wait needed).
        stream_one_row(eo, out, base + 3, last0, last1, lane);
    } else {
        // ================= STREAM consumer =================
        const int g    = warp - 4;
        const int base = cta_base + 4 * g;

        // Wait for pair 0 of gate warp g -> stream rows base, base+1.
        if (lane == 0) {
            while (((volatile int*)s_flag)[2 * g] == 0) __nanosleep(32);
        }
        __syncwarp();
        __threadfence_block();
        int a0 = s_i0[4 * g + 0], a1 = s_i1[4 * g + 0];
        int b0 = s_i0[4 * g + 1], b1 = s_i1[4 * g + 1];
        stream_two_rows(eo, out, base, a0, a1, base + 1, b0, b1, lane);

        // Wait for pair 1 -> stream row base+2 (base+3 handled by producer).
        if (lane == 0) {
            while (((volatile int*)s_flag)[2 * g + 1] == 0) __nanosleep(32);
        }
        __syncwarp();
        __threadfence_block();
        int c0 = s_i0[4 * g + 2], c1 = s_i1[4 * g + 2];
        stream_one_row(eo, out, base + 2, c0, c1, lane);
    }

    // ---- Aux finale (single barrier) ----
    __syncthreads();
    if (warp == 0) {
        int is_last = 0;
        if (lane == 0) {
            float s = 0.0f;
#pragma unroll
            for (int i = 0; i < ROWS_PER_CTA; i++) s += s_aux[i];
            g_aux_part[blockIdx.x] = s;
            __threadfence();
            unsigned p = atomicAdd(&g_ctr, 1u);
            is_last = (p == NCTA - 1);
        }
        is_last = __shfl_sync(0xffffffffu, is_last, 0);
        if (is_last) {
            double s = 0.0;
#pragma unroll
            for (int k = 0; k < NCTA / 32; k++)
                s += (double)__ldcg(&g_aux_part[lane + 32 * k]);
#pragma unroll
            for (int off = 16; off > 0; off >>= 1)
                s += __shfl_xor_sync(0xffffffffu, s, off);
            if (lane == 0) {
                out[out_size - 1] = -(float)(s / (double)BT);
                g_ctr = 0;                    // reset for next graph replay
            }
        }
    }
}

extern "C" void kernel_launch(void* const* d_in, const int* in_sizes, int n_in,
                              void* d_out, int out_size) {
    const float* x        = (const float*)d_in[0];
    const float* eo       = (const float*)d_in[1];
    const float* rewards  = (const float*)d_in[2];
    const float* W        = (const float*)d_in[3];
    const float* bias     = (const float*)d_in[4];
    const float* baseline = (const float*)d_in[5];
    const float* noise    = (const float*)d_in[6];
    // d_in[7] = top_k (K=2 hardcoded to match problem shapes)
    float* out = (float*)d_out;

    rlgate_main_kernel<<<NCTA, TPB>>>(x, eo, rewards, W, bias, baseline, noise,
                                      out, out_size);
}